// round 2
// baseline (speedup 1.0000x reference)
#include <cuda_runtime.h>
#include <cstdint>

// DTW: input x[65536], kernel k[512].
// ac[i][j] = min(ac[i-1][j-1], ac[i-1][j], ac[i][j-1]) + (k[j]-x[i])^2
// row 0 = cumsum of d[0][:], out[i] = ac[i][511].
//
// Wavefront over coarse tiles: 256 threads, thread p owns columns [2p, 2p+2).
// At step s, thread p computes rows [8(s-p), 8(s-p)+8) for its 2 columns.
// Right-edge values (column 2p+1, 8 rows) are passed to thread p+1 through
// double-buffered shared memory; one __syncthreads per step.
// x is streamed through a shared-memory ring refilled every 64 steps.

#define N_IN        65536
#define K_LEN       512
#define T_COL       2
#define P_THREADS   (K_LEN / T_COL)      // 256 threads, 8 warps
#define R_ROWS      8
#define STEPS_ACT   (N_IN / R_ROWS)      // 8192 active steps per thread
#define TOTAL_STEPS (STEPS_ACT + P_THREADS - 1)  // 8447
#define RING        4096
#define RING_MASK   (RING - 1)

__global__ __launch_bounds__(P_THREADS, 1)
void dtw_wavefront_kernel(const float* __restrict__ x,
                          const float* __restrict__ kern,
                          float* __restrict__ out)
{
    __shared__ float  ring[RING];                 // 16 KB x window
    __shared__ float4 edge[2][P_THREADS][2];      // 16 KB boundary exchange

    const int   p   = (int)threadIdx.x;
    const float INF = __int_as_float(0x7f800000);

    // Preload x rows [0, 2048) into the ring (512 float4s, 2 per thread).
    {
        const float4* xin4 = (const float4*)x;
        float4* r4 = (float4*)ring;
        r4[p]       = xin4[p];
        r4[p + 256] = xin4[p + 256];
    }

    const float kk0 = kern[2 * p];
    const float kk1 = kern[2 * p + 1];

    // DP state: previous-row values for my 2 columns, and the diag boundary
    // ac[last_row][2p-1] received from the left neighbor.
    float pv0 = INF, pv1 = INF, dlast = INF;

    __syncthreads();

    for (int s = 0; s < TOTAL_STEPS; ++s) {
        const int  par    = s & 1;
        const int  rbase  = (s - p) * R_ROWS;
        const bool active = (s >= p) && ((s - p) < STEPS_ACT);

        if (active) {
            // ---- boundary values from left neighbor (8 rows) ----
            // lleft[rr] = ac[rbase+rr][2p-1] used as the "left" term
            // ldg [rr] = same value used as "diag" for the NEXT row.
            // For p==0 the true ac[r][-1] is +INF for every r; the virtual 0
            // at (row 0, col -1) exists ONLY for the left-use at cell (0,0).
            float lleft[R_ROWS], ldg[R_ROWS];
            if (p == 0) {
                #pragma unroll
                for (int i = 0; i < R_ROWS; ++i) { lleft[i] = INF; ldg[i] = INF; }
                if (s == 0) lleft[0] = 0.0f;   // starts the row-0 cumsum
            } else {
                float4 La = edge[par ^ 1][p - 1][0];
                float4 Lb = edge[par ^ 1][p - 1][1];
                lleft[0] = La.x; lleft[1] = La.y; lleft[2] = La.z; lleft[3] = La.w;
                lleft[4] = Lb.x; lleft[5] = Lb.y; lleft[6] = Lb.z; lleft[7] = Lb.w;
                #pragma unroll
                for (int i = 0; i < R_ROWS; ++i) ldg[i] = lleft[i];
            }

            // ---- x values for my 8 rows (ring is 8-aligned per step) ----
            const float4* xr = (const float4*)&ring[rbase & RING_MASK];
            float4 xa = xr[0], xb = xr[1];
            float xs[R_ROWS] = {xa.x, xa.y, xa.z, xa.w, xb.x, xb.y, xb.z, xb.w};

            // ---- 8 rows x 2 columns of DP cells ----
            float ev[R_ROWS];
            float dg = dlast;     // ac[rbase-1][2p-1]
            #pragma unroll
            for (int rr = 0; rr < R_ROWS; ++rr) {
                const float xv = xs[rr];
                float t0 = kk0 - xv; const float d0 = t0 * t0;
                float t1 = kk1 - xv; const float d1 = t1 * t1;
                const float Lr = lleft[rr];
                // col 2p:   diag=dg, up=pv0, left=Lr
                const float v0 = fminf(fminf(dg, pv0), Lr) + d0;
                // col 2p+1: diag=pv0(old), up=pv1(old), left=v0
                const float v1 = fminf(fminf(pv0, pv1), v0) + d1;
                dg  = ldg[rr];
                pv0 = v0;
                pv1 = v1;
                ev[rr] = v1;
            }
            dlast = dg;           // = ac[rbase+7][2p-1]

            // ---- publish my right edge for thread p+1 ----
            edge[par][p][0] = make_float4(ev[0], ev[1], ev[2], ev[3]);
            edge[par][p][1] = make_float4(ev[4], ev[5], ev[6], ev[7]);

            // ---- last thread owns column 511 -> output ----
            if (p == P_THREADS - 1) {
                float4* o4 = (float4*)&out[rbase];
                o4[0] = make_float4(ev[0], ev[1], ev[2], ev[3]);
                o4[1] = make_float4(ev[4], ev[5], ev[6], ev[7]);
            }
        }

        // ---- ring refill: every 64 steps load 512 new x values ----
        if ((s & 63) == 0 && s != 0) {
            const int base = 8 * s + 1536;          // rows [base, base+512)
            int i0 = base + 2 * p;
            int i1 = i0 + 1;
            const float a = x[i0 < N_IN ? i0 : (N_IN - 1)];
            const float b = x[i1 < N_IN ? i1 : (N_IN - 1)];
            const int slot = (base & RING_MASK) + 2 * p;
            ring[slot]     = a;
            ring[slot + 1] = b;
        }

        __syncthreads();
    }
}

extern "C" void kernel_launch(void* const* d_in, const int* in_sizes, int n_in,
                              void* d_out, int out_size)
{
    const float* x = (const float*)d_in[0];   // input  [65536]
    const float* k = (const float*)d_in[1];   // kernel [512]
    float* out = (float*)d_out;               // [65536] float32

    dtw_wavefront_kernel<<<1, P_THREADS>>>(x, k, out);
}

// round 3
// speedup vs baseline: 1.5930x; 1.5930x over previous
#include <cuda_runtime.h>

// DTW 65536 x 512, 4-CTA column-pipelined wavefront.
// ac[r][j] = min(ac[r-1][j-1], ac[r-1][j], ac[r][j-1]) + (k[j]-x[r])^2
// Column j is owned by CTA j/128, warp (j%128)/32, lane j%32.
// Lane processes R=8 rows per tick; column j runs 1 tick behind column j-1.
//   intra-warp  handoff: shfl.up of previous tick's outputs
//   intra-CTA   handoff: double-buffered smem slot + per-tick __syncthreads
//   cross-CTA   handoff: __device__ global edge array + release/acquire flag,
//                        staged into smem in 64-tick chunks (double-buffered)

#define N_ROWS   65536
#define KLEN     512
#define NCTA     4
#define NWARP    4
#define NTHR     (NWARP * 32)          // 128
#define R        8
#define NTICK    (N_ROWS / R)          // 8192
#define NITER    (NTICK + NTHR - 1)    // 8319
#define RING     2048
#define RINGM    (RING - 1)
#define CHUNK    64                    // ticks per cross-CTA chunk (512 rows)

__device__ __align__(16) float g_edge[NCTA - 1][N_ROWS];
__device__ int g_flag[NCTA - 1];

__global__ void dtw_init_flags()
{
    if (threadIdx.x < NCTA - 1) g_flag[threadIdx.x] = 0;
}

__device__ __forceinline__ int flag_acquire(const int* p)
{
    int v;
    asm volatile("ld.acquire.gpu.global.b32 %0, [%1];" : "=r"(v) : "l"(p) : "memory");
    return v;
}

__device__ __forceinline__ void flag_release(int* p, int v)
{
    asm volatile("st.release.gpu.global.b32 [%0], %1;" :: "l"(p), "r"(v) : "memory");
}

__global__ __launch_bounds__(NTHR, 1)
void dtw_pipe_kernel(const float* __restrict__ x,
                     const float* __restrict__ kern,
                     float* __restrict__ out)
{
    __shared__ __align__(16) float  ring[RING];             // 8 KB x window
    __shared__ __align__(16) float  lbuf[2][CHUNK * R];     // 4 KB boundary staging
    __shared__ float4 edgebuf[2][NWARP][2];                 // intra-CTA handoff

    const int   c   = (int)blockIdx.x;
    const int   tid = (int)threadIdx.x;
    const int   w   = tid >> 5;
    const int   l   = tid & 31;
    const float INF = __int_as_float(0x7f800000);

    const float kv = kern[c * NTHR + tid];   // my column's kernel value

    // preload x rows [0, 512)
    ((float4*)ring)[tid] = ((const float4*)x)[tid];

    // pre-fetch cross-CTA boundary chunk 0 (ticks [0, 64))
    if (c > 0) {
        if (tid == 0) {
            while (flag_acquire(&g_flag[c - 1]) < CHUNK) { }
        }
        __syncthreads();
        ((float4*)lbuf[0])[tid] = ((const float4*)g_edge[c - 1])[tid];
    }
    __syncthreads();

    float ev[R];
    #pragma unroll
    for (int r = 0; r < R; ++r) ev[r] = 0.0f;
    float vprev = INF, dlast = INF;

    for (int i = 0; i < NITER; ++i) {
        // ---- shuffle previous tick's outputs before overwriting ev ----
        float Lsh[R];
        #pragma unroll
        for (int r = 0; r < R; ++r)
            Lsh[r] = __shfl_up_sync(0xffffffffu, ev[r], 1);

        // ---- chunk maintenance every 64 ticks (condition uniform per CTA) ----
        if ((i & (CHUNK - 1)) == 0) {
            // x refill: rows [8i+512, 8i+1024)
            const int r0 = 8 * i + 512 + 4 * tid;
            float4 xv4;
            const bool xok = (r0 < N_ROWS);
            if (xok) xv4 = *(const float4*)(x + r0);

            // boundary fetch: ticks [i+64, i+128)
            if (c > 0) {
                const int base = i + CHUNK;
                if (base < NTICK) {
                    if (tid == 0) {
                        const int need = min(base + CHUNK, NTICK);
                        while (flag_acquire(&g_flag[c - 1]) < need) { }
                    }
                    __syncthreads();
                    ((float4*)lbuf[((i >> 6) + 1) & 1])[tid] =
                        *(const float4*)(g_edge[c - 1] + base * R + 4 * tid);
                }
            }
            if (xok) *(float4*)(ring + (r0 & RINGM)) = xv4;
            // staged data is first consumed >= 64 iterations later; the
            // per-iteration barrier below orders the STS before those reads.
        }

        const int  t      = i - tid;               // my tick (offset = tid)
        const bool active = (t >= 0) && (t < NTICK);

        // ---- left-neighbor values for rows [8t, 8t+8) ----
        float L[R];
        if (l == 0) {
            if (w == 0) {
                if (c == 0) {
                    #pragma unroll
                    for (int r = 0; r < R; ++r) L[r] = INF;
                    if (i == 0) L[0] = 0.0f;       // virtual 0 at (row 0, col -1)
                } else {
                    const float4* lb = (const float4*)&lbuf[(i >> 6) & 1][(i & (CHUNK - 1)) * R];
                    float4 a = lb[0], b = lb[1];
                    L[0] = a.x; L[1] = a.y; L[2] = a.z; L[3] = a.w;
                    L[4] = b.x; L[5] = b.y; L[6] = b.z; L[7] = b.w;
                }
            } else {
                float4 a = edgebuf[(i & 1) ^ 1][w - 1][0];
                float4 b = edgebuf[(i & 1) ^ 1][w - 1][1];
                L[0] = a.x; L[1] = a.y; L[2] = a.z; L[3] = a.w;
                L[4] = b.x; L[5] = b.y; L[6] = b.z; L[7] = b.w;
            }
        } else {
            #pragma unroll
            for (int r = 0; r < R; ++r) L[r] = Lsh[r];
        }

        if (active) {
            // x values for my 8 rows
            const float* xr = ring + ((t * R) & RINGM);
            const float4 xa = *(const float4*)xr;
            const float4 xb = *(const float4*)(xr + 4);
            const float xs[R] = {xa.x, xa.y, xa.z, xa.w, xb.x, xb.y, xb.z, xb.w};

            // off-chain precompute: m[r] = min(diag, left)
            float m[R];
            m[0] = fminf(dlast, L[0]);
            #pragma unroll
            for (int r = 1; r < R; ++r) m[r] = fminf(L[r - 1], L[r]);

            // serial chain: v = min(m, vprev) + d   (8 cyc/row)
            float vp = vprev;
            #pragma unroll
            for (int r = 0; r < R; ++r) {
                const float tt = kv - xs[r];
                const float d  = tt * tt;
                vp = fminf(m[r], vp) + d;
                ev[r] = vp;
            }
            vprev = vp;
            dlast = L[R - 1];

            // ---- publish my right edge ----
            if (l == 31) {
                const float4 a = make_float4(ev[0], ev[1], ev[2], ev[3]);
                const float4 b = make_float4(ev[4], ev[5], ev[6], ev[7]);
                if (w < NWARP - 1) {
                    edgebuf[i & 1][w][0] = a;
                    edgebuf[i & 1][w][1] = b;
                } else if (c < NCTA - 1) {
                    *(float4*)(g_edge[c] + t * R)     = a;
                    *(float4*)(g_edge[c] + t * R + 4) = b;
                    if ((t & 15) == 15)
                        flag_release(&g_flag[c], t + 1);
                } else {
                    *(float4*)(out + t * R)     = a;
                    *(float4*)(out + t * R + 4) = b;
                }
            }
        }

        __syncthreads();
    }
}

extern "C" void kernel_launch(void* const* d_in, const int* in_sizes, int n_in,
                              void* d_out, int out_size)
{
    const float* x = (const float*)d_in[0];   // input  [65536]
    const float* k = (const float*)d_in[1];   // kernel [512]
    float* out = (float*)d_out;               // [65536] float32

    dtw_init_flags<<<1, 32>>>();
    dtw_pipe_kernel<<<NCTA, NTHR>>>(x, k, out);
}